// round 7
// baseline (speedup 1.0000x reference)
#include <cuda_runtime.h>
#include <cuda_fp16.h>
#include <cstdint>

// ---------------- problem constants ----------------
static constexpr int B = 512, S = 128, D = 512, A = 128;
static constexpr float EPS = 1e-7f;

// ---------------- device scratch (no allocs allowed) ----------------
__device__ __align__(16) __half g_wt[A * D];   // W^T fp16  [a][k]
__device__ float g_kv[B * S];
__device__ float g_mv;

// ---------------- gemm tiling ----------------
static constexpr int KC     = 32;              // k per chunk
static constexpr int NCHUNK = D / KC;          // 16
static constexpr int STAGES = 3;

// X stage: [128 rows][40 f32] (32 data + 8 pad) = 160 B/row -> 20480 B
// W stage: [128 rows][40 h]   (32 data + 8 pad) =  80 B/row -> 10240 B
static constexpr int XROWB  = 40 * 4;          // 160
static constexpr int WROWB  = 40 * 2;          // 80
static constexpr int XBUF_B = 128 * XROWB;     // 20480
static constexpr int WBUF_B = 128 * WROWB;     // 10240
static constexpr int OFF_XF   = 0;
static constexpr int OFF_WH   = OFF_XF + STAGES * XBUF_B;   // 61440
static constexpr int OFF_BIAS = OFF_WH + STAGES * WBUF_B;   // 92160
static constexpr int OFF_U    = OFF_BIAS + 512;
static constexpr int OFF_PART = OFF_U + 512;                // float[128][2]
static constexpr int SMEM_TOTAL = OFF_PART + 1024;          // 94208

// ---------------- baseline-ISA helpers (sm_100 plain) ----------------
__device__ __forceinline__ uint32_t smem_u32(const void* p) {
    return (uint32_t)__cvta_generic_to_shared(p);
}

#define CP_ASYNC16(dst, src) \
    asm volatile("cp.async.cg.shared.global [%0], [%1], 16;" :: "r"(dst), "l"(src))
#define CP_COMMIT() asm volatile("cp.async.commit_group;")
#define CP_WAIT_1() asm volatile("cp.async.wait_group 1;")

#define LDSM_X4(r, addr) \
    asm volatile("ldmatrix.sync.aligned.m8n8.x4.shared.b16 {%0,%1,%2,%3}, [%4];" \
        : "=r"((r)[0]), "=r"((r)[1]), "=r"((r)[2]), "=r"((r)[3]) : "r"(addr))

#define MMA_F16(d, a, b0, b1) \
    asm volatile("mma.sync.aligned.m16n8k16.row.col.f32.f16.f16.f32 " \
        "{%0,%1,%2,%3}, {%4,%5,%6,%7}, {%8,%9}, {%0,%1,%2,%3};" \
        : "+f"((d)[0]), "+f"((d)[1]), "+f"((d)[2]), "+f"((d)[3]) \
        : "r"((a)[0]), "r"((a)[1]), "r"((a)[2]), "r"((a)[3]), "r"(b0), "r"(b1))

__device__ __forceinline__ uint32_t f2h2(float a, float b) {
    __half2 h = __floats2half2_rn(a, b);
    return *(uint32_t*)&h;
}

__device__ __forceinline__ float fast_tanh(float x) {
    float a = fabsf(x);
    float t = __expf(-2.0f * a);
    float r = (1.0f - t) / (1.0f + t);
    return copysignf(r, x);
}

// ---------------- kernel 0: transpose W to fp16 ----------------
__global__ void prep_w_kernel(const float* __restrict__ W) {
    int idx = blockIdx.x * blockDim.x + threadIdx.x;
    if (idx < D * A) {
        int k = idx / A, a = idx % A;
        g_wt[a * D + k] = __float2half_rn(W[idx]);
    }
}

// ---------------- kernel 1: fused GEMM + tanh + kv ----------------
// CTA = one batch. 3-stage cp.async pipeline over 16 k-chunks of 32.
__global__ __launch_bounds__(256, 2)
void gemm_kv_kernel(const float* __restrict__ x,
                    const float* __restrict__ bias,
                    const float* __restrict__ u) {
    extern __shared__ char smem[];
    const uint32_t sb = smem_u32(smem);
    const int tid = threadIdx.x;
    const int wid = tid >> 5;
    const int l   = tid & 31;
    const int b   = blockIdx.x;

    if (tid < A) {
        *(float*)(smem + OFF_BIAS + tid * 4) = bias[tid];
        *(float*)(smem + OFF_U + tid * 4) = u[tid];
    }

    const int wm = wid >> 1, wn = wid & 1;
    const int m0 = wm * 32, n0 = wn * 64;

    const float* xb = x + (size_t)b * S * D;

    // A-fragment lane geometry
    const int ar = l >> 2;                  // 0..7
    const int ac = (l & 3) << 1;            // 0,2,4,6
    // B-fragment ldmatrix pointer (within a W stage)
    const uint32_t bOff = (uint32_t)((n0 + ((l >> 4) << 3) + (l & 7)) * WROWB
                                     + (((l >> 3) & 1) << 3) * 2);

    // cp.async slot geometry: X 1024 ops (4/thread), W 512 ops (2/thread)
    const int xr0 = tid >> 3, xj = tid & 7;       // + t*32 rows
    const int wr0 = tid >> 2, wj = tid & 3;       // + t*64 rows

    float acc[2][8][4];
    #pragma unroll
    for (int mt = 0; mt < 2; mt++)
        #pragma unroll
        for (int nt = 0; nt < 8; nt++)
            #pragma unroll
            for (int q = 0; q < 4; q++) acc[mt][nt][q] = 0.0f;

    // ---- prologue: issue chunks 0 and 1 ----
    #pragma unroll
    for (int pc = 0; pc < 2; pc++) {
        const int kk = pc * KC;
        const uint32_t xB = sb + OFF_XF + pc * XBUF_B;
        const uint32_t wB = sb + OFF_WH + pc * WBUF_B;
        #pragma unroll
        for (int t = 0; t < 4; t++) {
            int row = xr0 + t * 32;
            CP_ASYNC16(xB + row * XROWB + xj * 16,
                       (const char*)(xb + (size_t)row * D + kk) + xj * 16);
        }
        #pragma unroll
        for (int t = 0; t < 2; t++) {
            int row = wr0 + t * 64;
            CP_ASYNC16(wB + row * WROWB + wj * 16,
                       (const char*)(g_wt + (size_t)row * D + kk) + wj * 16);
        }
        CP_COMMIT();
    }

    #pragma unroll 1
    for (int c = 0; c < NCHUNK; c++) {
        CP_WAIT_1();          // all but newest group done -> chunk c arrived
        __syncthreads();

        if (c + 2 < NCHUNK) {
            const int kk = (c + 2) * KC;
            const uint32_t xB = sb + OFF_XF + ((c + 2) % STAGES) * XBUF_B;
            const uint32_t wB = sb + OFF_WH + ((c + 2) % STAGES) * WBUF_B;
            #pragma unroll
            for (int t = 0; t < 4; t++) {
                int row = xr0 + t * 32;
                CP_ASYNC16(xB + row * XROWB + xj * 16,
                           (const char*)(xb + (size_t)row * D + kk) + xj * 16);
            }
            #pragma unroll
            for (int t = 0; t < 2; t++) {
                int row = wr0 + t * 64;
                CP_ASYNC16(wB + row * WROWB + wj * 16,
                           (const char*)(g_wt + (size_t)row * D + kk) + wj * 16);
            }
        }
        CP_COMMIT();          // always commit (empty groups keep wait math valid)

        const uint32_t xF = sb + OFF_XF + (c % STAGES) * XBUF_B;
        const uint32_t wH = sb + OFF_WH + (c % STAGES) * WBUF_B;

        #pragma unroll
        for (int ks = 0; ks < 2; ks++) {
            const int kc = ks * 16;
            uint32_t ah[2][4], bb[4][4];
            #pragma unroll
            for (int mt = 0; mt < 2; mt++) {
                const uint32_t boff = (uint32_t)((m0 + mt * 16 + ar) * XROWB
                                                 + (kc + ac) * 4) + (xF - sb);
                float2 v0 = *(const float2*)(smem + boff);
                float2 v1 = *(const float2*)(smem + boff + 8 * XROWB);
                float2 v2 = *(const float2*)(smem + boff + 32);
                float2 v3 = *(const float2*)(smem + boff + 8 * XROWB + 32);
                ah[mt][0] = f2h2(v0.x, v0.y);
                ah[mt][1] = f2h2(v1.x, v1.y);
                ah[mt][2] = f2h2(v2.x, v2.y);
                ah[mt][3] = f2h2(v3.x, v3.y);
            }
            #pragma unroll
            for (int nb = 0; nb < 4; nb++)
                LDSM_X4(bb[nb], wH + bOff + nb * (16 * WROWB) + kc * 2);
            #pragma unroll
            for (int mt = 0; mt < 2; mt++)
                #pragma unroll
                for (int nb = 0; nb < 4; nb++) {
                    MMA_F16(acc[mt][2 * nb],     ah[mt], bb[nb][0], bb[nb][1]);
                    MMA_F16(acc[mt][2 * nb + 1], ah[mt], bb[nb][2], bb[nb][3]);
                }
        }
    }
    __syncthreads();

    // ---- epilogue: kv[m] = sum_n tanh(C[m][n] + bias[n]) * u[n] ----
    float rs[2][2] = {{0.0f, 0.0f}, {0.0f, 0.0f}};
    #pragma unroll
    for (int mt = 0; mt < 2; mt++) {
        #pragma unroll
        for (int nt = 0; nt < 8; nt++) {
            int n = n0 + nt * 8 + ((l & 3) << 1);
            float b0v = *(const float*)(smem + OFF_BIAS + n * 4);
            float b1v = *(const float*)(smem + OFF_BIAS + (n + 1) * 4);
            float u0v = *(const float*)(smem + OFF_U + n * 4);
            float u1v = *(const float*)(smem + OFF_U + (n + 1) * 4);
            rs[mt][0] += fast_tanh(acc[mt][nt][0] + b0v) * u0v
                       + fast_tanh(acc[mt][nt][1] + b1v) * u1v;
            rs[mt][1] += fast_tanh(acc[mt][nt][2] + b0v) * u0v
                       + fast_tanh(acc[mt][nt][3] + b1v) * u1v;
        }
    }
    #pragma unroll
    for (int mt = 0; mt < 2; mt++)
        #pragma unroll
        for (int h = 0; h < 2; h++) {
            float v = rs[mt][h];
            v += __shfl_xor_sync(0xFFFFFFFFu, v, 1);
            v += __shfl_xor_sync(0xFFFFFFFFu, v, 2);
            if ((l & 3) == 0) {
                int row = m0 + mt * 16 + h * 8 + (l >> 2);
                *(float*)(smem + OFF_PART + (row * 2 + wn) * 4) = v;
            }
        }
    __syncthreads();
    if (tid < S) {
        float kv = *(const float*)(smem + OFF_PART + (tid * 2) * 4)
                 + *(const float*)(smem + OFF_PART + (tid * 2 + 1) * 4);
        g_kv[b * S + tid] = kv;
    }
}

// ---------------- kernel 2: global sum of kv (double accum) ----------------
__global__ void reduce_kernel() {
    __shared__ double ssum[32];
    double acc = 0.0;
    for (int i = threadIdx.x; i < B * S; i += 1024)
        acc += (double)g_kv[i];
    #pragma unroll
    for (int o = 16; o > 0; o >>= 1)
        acc += __shfl_xor_sync(0xFFFFFFFFu, acc, o);
    if ((threadIdx.x & 31) == 0) ssum[threadIdx.x >> 5] = acc;
    __syncthreads();
    if (threadIdx.x < 32) {
        double v = ssum[threadIdx.x];
        #pragma unroll
        for (int o = 16; o > 0; o >>= 1)
            v += __shfl_xor_sync(0xFFFFFFFFu, v, o);
        if (threadIdx.x == 0) g_mv = (float)v;
    }
}

// ---------------- kernel 3: softmax + weighted pooling (float4) ----------
// Grid {B, 2}: each y-half covers 256 d-cols (64 float4), s split 4-way,
// two interleaved accumulators for deeper MLP.
__global__ __launch_bounds__(256)
void softmax_pool_kernel(const float* __restrict__ x,
                         const float* __restrict__ mask,
                         float* __restrict__ out) {
    __shared__ float sprob[S];
    __shared__ float ssum;
    __shared__ float4 spart[4][64];
    const int tid = threadIdx.x;
    const int b = blockIdx.x;
    const int half = blockIdx.y;
    const float mv = g_mv;

    if (tid < S) {
        float e = (expf(g_kv[b * S + tid] - mv) + EPS) * mask[b * S + tid];
        sprob[tid] = e;
    }
    __syncthreads();
    if (tid < 32) {
        float v = sprob[tid] + sprob[tid + 32] + sprob[tid + 64] + sprob[tid + 96];
        #pragma unroll
        for (int o = 16; o > 0; o >>= 1)
            v += __shfl_xor_sync(0xFFFFFFFFu, v, o);
        if (tid == 0) ssum = v;
    }
    __syncthreads();
    const float inv = 1.0f / (ssum + EPS);
    if (tid < S) {
        float p = sprob[tid] * inv;
        sprob[tid] = p;
        if (half == 0) out[B * D + b * S + tid] = p;   // prob output
    }
    __syncthreads();

    // pooling: thread = (sq, dq); dq in [0,64) float4 cols, sq in [0,4)
    const int dq = tid & 63;
    const int sq = tid >> 6;
    const float* xb = x + (size_t)b * S * D + half * 256;
    float4 a0 = make_float4(0.f, 0.f, 0.f, 0.f);
    float4 a1 = make_float4(0.f, 0.f, 0.f, 0.f);
    const int s0 = sq * 32;
    #pragma unroll 16
    for (int s = 0; s < 16; s++) {
        float4 v0 = *(const float4*)(xb + (size_t)(s0 + s) * D + dq * 4);
        float4 v1 = *(const float4*)(xb + (size_t)(s0 + s + 16) * D + dq * 4);
        float p0 = sprob[s0 + s], p1 = sprob[s0 + s + 16];
        a0.x += v0.x * p0; a0.y += v0.y * p0; a0.z += v0.z * p0; a0.w += v0.w * p0;
        a1.x += v1.x * p1; a1.y += v1.y * p1; a1.z += v1.z * p1; a1.w += v1.w * p1;
    }
    spart[sq][dq] = make_float4(a0.x + a1.x, a0.y + a1.y, a0.z + a1.z, a0.w + a1.w);
    __syncthreads();
    if (tid < 64) {
        float4 p0 = spart[0][tid], p1 = spart[1][tid];
        float4 p2 = spart[2][tid], p3 = spart[3][tid];
        float4 r = make_float4(p0.x + p1.x + p2.x + p3.x,
                               p0.y + p1.y + p2.y + p3.y,
                               p0.z + p1.z + p2.z + p3.z,
                               p0.w + p1.w + p2.w + p3.w);
        *(float4*)(out + b * D + half * 256 + tid * 4) = r;
    }
}

// ---------------- launcher ----------------
extern "C" void kernel_launch(void* const* d_in, const int* in_sizes, int n_in,
                              void* d_out, int out_size) {
    const float* x    = (const float*)d_in[0];  // inputs  [B,S,D]
    const float* mask = (const float*)d_in[1];  // mask    [B,S,1]
    const float* W    = (const float*)d_in[2];  // kernel  [D,A]
    const float* bias = (const float*)d_in[3];  // bias    [A]
    const float* u    = (const float*)d_in[4];  // u_ctx   [A,1]
    float* out = (float*)d_out;                 // pooled [B,D] ++ prob [B,S]

    cudaFuncSetAttribute(gemm_kv_kernel,
                         cudaFuncAttributeMaxDynamicSharedMemorySize, SMEM_TOTAL);

    prep_w_kernel<<<(D * A + 255) / 256, 256>>>(W);
    gemm_kv_kernel<<<B, 256, SMEM_TOTAL>>>(x, bias, u);
    reduce_kernel<<<1, 1024>>>();
    softmax_pool_kernel<<<dim3(B, 2), 256>>>(x, mask, out);
}